// round 1
// baseline (speedup 1.0000x reference)
#include <cuda_runtime.h>
#include <math.h>

// Problem constants
#define B_     8
#define CIN_   64
#define COUT_  128
#define KH_    3
#define KW_    3
#define K_     9           // KH*KW
#define H_     64
#define W_     64
#define HO_    64
#define WO_    64
#define P_     4096        // HO*WO
#define CK_    576         // CIN*K

// col scratch: [B][CIN*K][P] fp32 = 8*576*4096*4 = 75.5 MB
__device__ float g_col[B_ * CK_ * P_];

// ---------------------------------------------------------------------------
// Kernel 1: deformable im2col with bilinear sampling.
// One thread per (b, k, p). Bilinear weights computed once, reused for 64 cin.
// ---------------------------------------------------------------------------
__global__ void im2col_kernel(const float* __restrict__ rgb,
                              const float* __restrict__ offsets) {
    int idx = blockIdx.x * blockDim.x + threadIdx.x;
    if (idx >= B_ * K_ * P_) return;

    int p  = idx & (P_ - 1);
    int bk = idx >> 12;          // /4096
    int k  = bk % K_;
    int b  = bk / K_;

    int oy = p >> 6;             // /64
    int ox = p & 63;

    // offsets: [B][2*K][H][W]; channel 2k = dy, 2k+1 = dx
    const float* offb = offsets + (size_t)b * 2 * K_ * P_;
    float dy = offb[(2 * k    ) * P_ + p];
    float dx = offb[(2 * k + 1) * P_ + p];

    float y = (float)(oy - 1 + k / KW_) + dy;
    float x = (float)(ox - 1 + k % KW_) + dx;

    float y0f = floorf(y);
    float x0f = floorf(x);
    float fy = y - y0f;
    float fx = x - x0f;
    int y0 = (int)y0f;
    int x0 = (int)x0f;
    int y1 = y0 + 1;
    int x1 = x0 + 1;

    float w00 = (1.f - fy) * (1.f - fx);
    float w01 = (1.f - fy) * fx;
    float w10 = fy * (1.f - fx);
    float w11 = fy * fx;

    bool vy0 = (y0 >= 0) & (y0 < H_);
    bool vy1 = (y1 >= 0) & (y1 < H_);
    bool vx0 = (x0 >= 0) & (x0 < W_);
    bool vx1 = (x1 >= 0) & (x1 < W_);

    if (!(vy0 & vx0)) w00 = 0.f;
    if (!(vy0 & vx1)) w01 = 0.f;
    if (!(vy1 & vx0)) w10 = 0.f;
    if (!(vy1 & vx1)) w11 = 0.f;

    int cy0 = min(max(y0, 0), H_ - 1);
    int cy1 = min(max(y1, 0), H_ - 1);
    int cx0 = min(max(x0, 0), W_ - 1);
    int cx1 = min(max(x1, 0), W_ - 1);

    int i00 = cy0 * W_ + cx0;
    int i01 = cy0 * W_ + cx1;
    int i10 = cy1 * W_ + cx0;
    int i11 = cy1 * W_ + cx1;

    const float* img = rgb + (size_t)b * CIN_ * P_;
    float* colp = g_col + (size_t)b * CK_ * P_ + (size_t)k * P_ + p;

    #pragma unroll 4
    for (int c = 0; c < CIN_; c++) {
        const float* ch = img + c * P_;
        float v = w00 * ch[i00] + w01 * ch[i01]
                + w10 * ch[i10] + w11 * ch[i11];
        colp[(size_t)c * K_ * P_] = v;
    }
}

// ---------------------------------------------------------------------------
// Kernel 2: batched GEMM  out[b] = W[128x576] * col[b][576x4096] + bias
// Block tile 64(m) x 64(n), TK=16, 256 threads, 4x4 micro-tile/thread.
// ---------------------------------------------------------------------------
#define TM 64
#define TN 64
#define TK 16

__global__ __launch_bounds__(256)
void gemm_kernel(const float* __restrict__ weight,
                 const float* __restrict__ bias,
                 float* __restrict__ out) {
    __shared__ float As[TK][TM];      // [k][m]
    __shared__ float Bs[TK][TN + 4];  // [k][n], pad to dodge conflicts

    int b  = blockIdx.z;
    int m0 = blockIdx.y * TM;
    int n0 = blockIdx.x * TN;
    int tid = threadIdx.x;

    int tx = tid & 15;   // n-dir (16 * 4 = 64)
    int ty = tid >> 4;   // m-dir (16 * 4 = 64)

    const float* colb = g_col + (size_t)b * CK_ * P_;

    float acc[4][4];
    #pragma unroll
    for (int i = 0; i < 4; i++)
        #pragma unroll
        for (int j = 0; j < 4; j++) acc[i][j] = 0.f;

    for (int k0 = 0; k0 < CK_; k0 += TK) {
        // Load A tile: W[m0+m][k0+kk] -> As[kk][m].  64*16 = 1024 elems.
        #pragma unroll
        for (int t = tid; t < TM * TK; t += 256) {
            int m  = t >> 4;        // /16
            int kk = t & 15;
            As[kk][m] = weight[(size_t)(m0 + m) * CK_ + k0 + kk];
        }
        // Load B tile: col[k0+kk][n0+n] -> Bs[kk][n].  16*64 = 1024 elems.
        #pragma unroll
        for (int t = tid; t < TK * TN; t += 256) {
            int kk = t >> 6;        // /64
            int n  = t & 63;
            Bs[kk][n] = colb[(size_t)(k0 + kk) * P_ + n0 + n];
        }
        __syncthreads();

        #pragma unroll
        for (int kk = 0; kk < TK; kk++) {
            float ra[4], rb[4];
            #pragma unroll
            for (int i = 0; i < 4; i++) ra[i] = As[kk][ty * 4 + i];
            #pragma unroll
            for (int j = 0; j < 4; j++) rb[j] = Bs[kk][tx * 4 + j];
            #pragma unroll
            for (int i = 0; i < 4; i++)
                #pragma unroll
                for (int j = 0; j < 4; j++)
                    acc[i][j] = fmaf(ra[i], rb[j], acc[i][j]);
        }
        __syncthreads();
    }

    float* outb = out + (size_t)b * COUT_ * P_;
    #pragma unroll
    for (int i = 0; i < 4; i++) {
        int m = m0 + ty * 4 + i;
        float bv = bias[m];
        #pragma unroll
        for (int j = 0; j < 4; j++) {
            outb[(size_t)m * P_ + n0 + tx * 4 + j] = acc[i][j] + bv;
        }
    }
}

extern "C" void kernel_launch(void* const* d_in, const int* in_sizes, int n_in,
                              void* d_out, int out_size) {
    const float* rgb     = (const float*)d_in[0];
    const float* offsets = (const float*)d_in[1];
    const float* weight  = (const float*)d_in[2];
    const float* bias    = (const float*)d_in[3];
    float* out = (float*)d_out;

    {
        int total = B_ * K_ * P_;
        int threads = 256;
        int blocks = (total + threads - 1) / threads;
        im2col_kernel<<<blocks, threads>>>(rgb, offsets);
    }
    {
        dim3 grid(P_ / TN, COUT_ / TM, B_);   // 64 x 2 x 8
        gemm_kernel<<<grid, 256>>>(weight, bias, out);
    }
}

// round 2
// speedup vs baseline: 1.6213x; 1.6213x over previous
#include <cuda_runtime.h>
#include <math.h>

// Problem constants
#define B_     8
#define CIN_   64
#define COUT_  128
#define KH_    3
#define KW_    3
#define K_     9           // KH*KW
#define H_     64
#define W_     64
#define HO_    64
#define WO_    64
#define P_     4096        // HO*WO
#define CK_    576         // CIN*K

// col scratch: [B][CIN*K][P] fp32 = 8*576*4096*4 = 75.5 MB
__device__ float g_col[B_ * CK_ * P_];

// ---------------------------------------------------------------------------
// Kernel 1: deformable im2col with bilinear sampling.
// One thread per (b, k, p). Bilinear weights computed once, reused for 64 cin.
// ---------------------------------------------------------------------------
__global__ void im2col_kernel(const float* __restrict__ rgb,
                              const float* __restrict__ offsets) {
    int idx = blockIdx.x * blockDim.x + threadIdx.x;
    if (idx >= B_ * K_ * P_) return;

    int p  = idx & (P_ - 1);
    int bk = idx >> 12;          // /4096
    int k  = bk % K_;
    int b  = bk / K_;

    int oy = p >> 6;             // /64
    int ox = p & 63;

    // offsets: [B][2*K][H][W]; channel 2k = dy, 2k+1 = dx
    const float* offb = offsets + (size_t)b * 2 * K_ * P_;
    float dy = offb[(2 * k    ) * P_ + p];
    float dx = offb[(2 * k + 1) * P_ + p];

    float y = (float)(oy - 1 + k / KW_) + dy;
    float x = (float)(ox - 1 + k % KW_) + dx;

    float y0f = floorf(y);
    float x0f = floorf(x);
    float fy = y - y0f;
    float fx = x - x0f;
    int y0 = (int)y0f;
    int x0 = (int)x0f;
    int y1 = y0 + 1;
    int x1 = x0 + 1;

    float w00 = (1.f - fy) * (1.f - fx);
    float w01 = (1.f - fy) * fx;
    float w10 = fy * (1.f - fx);
    float w11 = fy * fx;

    bool vy0 = (y0 >= 0) & (y0 < H_);
    bool vy1 = (y1 >= 0) & (y1 < H_);
    bool vx0 = (x0 >= 0) & (x0 < W_);
    bool vx1 = (x1 >= 0) & (x1 < W_);

    if (!(vy0 & vx0)) w00 = 0.f;
    if (!(vy0 & vx1)) w01 = 0.f;
    if (!(vy1 & vx0)) w10 = 0.f;
    if (!(vy1 & vx1)) w11 = 0.f;

    int cy0 = min(max(y0, 0), H_ - 1);
    int cy1 = min(max(y1, 0), H_ - 1);
    int cx0 = min(max(x0, 0), W_ - 1);
    int cx1 = min(max(x1, 0), W_ - 1);

    int i00 = cy0 * W_ + cx0;
    int i01 = cy0 * W_ + cx1;
    int i10 = cy1 * W_ + cx0;
    int i11 = cy1 * W_ + cx1;

    const float* img = rgb + (size_t)b * CIN_ * P_;
    float* colp = g_col + (size_t)b * CK_ * P_ + (size_t)k * P_ + p;

    #pragma unroll 4
    for (int c = 0; c < CIN_; c++) {
        const float* ch = img + c * P_;
        float v = w00 * ch[i00] + w01 * ch[i01]
                + w10 * ch[i10] + w11 * ch[i11];
        colp[(size_t)c * K_ * P_] = v;
    }
}

// ---------------------------------------------------------------------------
// Kernel 2: batched GEMM  out[b] = W[128x576] * col[b][576x4096] + bias
// BM=128 x BN=128 block tile, BK=8, 256 threads, 8x8 micro-tile per thread,
// float4 everywhere, register-prefetch double buffering.
// ---------------------------------------------------------------------------
#define BM 128
#define BN 128
#define BK 8
#define LDA 132   // padded row length for As/Bs (conflict-free, still 16B aligned)

__global__ __launch_bounds__(256)
void gemm_kernel(const float* __restrict__ weight,
                 const float* __restrict__ bias,
                 float* __restrict__ out) {
    __shared__ float As[BK][LDA];   // [k][m]
    __shared__ float Bs[BK][LDA];   // [k][n]

    const int b   = blockIdx.z;
    const int n0  = blockIdx.x * BN;
    const int tid = threadIdx.x;

    const int tx = tid & 15;   // n-dir
    const int ty = tid >> 4;   // m-dir

    const float* colb = g_col + (size_t)b * CK_ * P_;

    // A-tile load mapping: 256 float4 = 128 rows x 2 chunks of k
    const int a_row = tid >> 1;          // 0..127  (m)
    const int a_kq  = (tid & 1) * 4;     // 0 or 4  (k offset)
    // B-tile load mapping: 256 float4 = 8 rows x 32 chunks of n
    const int b_kk  = tid >> 5;          // 0..7    (k)
    const int b_nq  = (tid & 31) * 4;    // 0..124  (n offset)

    float acc[8][8];
    #pragma unroll
    for (int i = 0; i < 8; i++)
        #pragma unroll
        for (int j = 0; j < 8; j++) acc[i][j] = 0.f;

    // prefetch first tile into registers
    float4 pa = *(const float4*)&weight[(size_t)a_row * CK_ + a_kq];
    float4 pb = *(const float4*)&colb[(size_t)b_kk * P_ + n0 + b_nq];

    for (int k0 = 0; k0 < CK_; k0 += BK) {
        // store prefetched tile to smem
        As[a_kq + 0][a_row] = pa.x;
        As[a_kq + 1][a_row] = pa.y;
        As[a_kq + 2][a_row] = pa.z;
        As[a_kq + 3][a_row] = pa.w;
        *(float4*)&Bs[b_kk][b_nq] = pb;
        __syncthreads();

        // prefetch next tile
        if (k0 + BK < CK_) {
            pa = *(const float4*)&weight[(size_t)a_row * CK_ + k0 + BK + a_kq];
            pb = *(const float4*)&colb[(size_t)(k0 + BK + b_kk) * P_ + n0 + b_nq];
        }

        // compute
        #pragma unroll
        for (int kk = 0; kk < BK; kk++) {
            float4 a0 = *(const float4*)&As[kk][ty * 4];
            float4 a1 = *(const float4*)&As[kk][64 + ty * 4];
            float4 b0 = *(const float4*)&Bs[kk][tx * 4];
            float4 b1 = *(const float4*)&Bs[kk][64 + tx * 4];
            float ra[8] = {a0.x, a0.y, a0.z, a0.w, a1.x, a1.y, a1.z, a1.w};
            float rb[8] = {b0.x, b0.y, b0.z, b0.w, b1.x, b1.y, b1.z, b1.w};
            #pragma unroll
            for (int i = 0; i < 8; i++)
                #pragma unroll
                for (int j = 0; j < 8; j++)
                    acc[i][j] = fmaf(ra[i], rb[j], acc[i][j]);
        }
        __syncthreads();
    }

    // epilogue: bias + float4 stores
    float* outb = out + (size_t)b * COUT_ * P_;
    #pragma unroll
    for (int i = 0; i < 8; i++) {
        int m = (i < 4) ? (ty * 4 + i) : (64 + ty * 4 + i - 4);
        float bv = bias[m];
        float4 v0 = make_float4(acc[i][0] + bv, acc[i][1] + bv,
                                acc[i][2] + bv, acc[i][3] + bv);
        float4 v1 = make_float4(acc[i][4] + bv, acc[i][5] + bv,
                                acc[i][6] + bv, acc[i][7] + bv);
        *(float4*)&outb[(size_t)m * P_ + n0 + tx * 4]      = v0;
        *(float4*)&outb[(size_t)m * P_ + n0 + 64 + tx * 4] = v1;
    }
}

extern "C" void kernel_launch(void* const* d_in, const int* in_sizes, int n_in,
                              void* d_out, int out_size) {
    const float* rgb     = (const float*)d_in[0];
    const float* offsets = (const float*)d_in[1];
    const float* weight  = (const float*)d_in[2];
    const float* bias    = (const float*)d_in[3];
    float* out = (float*)d_out;

    {
        int total = B_ * K_ * P_;
        int threads = 256;
        int blocks = (total + threads - 1) / threads;
        im2col_kernel<<<blocks, threads>>>(rgb, offsets);
    }
    {
        dim3 grid(P_ / BN, 1, B_);   // 32 x 1 x 8 = 256 blocks
        gemm_kernel<<<grid, 256>>>(weight, bias, out);
    }
}

// round 3
// speedup vs baseline: 2.5271x; 1.5586x over previous
#include <cuda_runtime.h>
#include <math.h>
#include <stdint.h>

// Problem constants
#define B_     8
#define CIN_   64
#define COUT_  128
#define KH_    3
#define KW_    3
#define K_     9           // KH*KW
#define H_     64
#define W_     64
#define HO_    64
#define WO_    64
#define P_     4096        // HO*WO
#define CK_    576         // CIN*K

// col scratch: [B][CIN*K][P] fp32 = 8*576*4096*4 = 75.5 MB
__device__ float g_col[B_ * CK_ * P_];

// ---------------------------------------------------------------------------
// Kernel 1: deformable im2col with bilinear sampling.
// ---------------------------------------------------------------------------
__global__ void im2col_kernel(const float* __restrict__ rgb,
                              const float* __restrict__ offsets) {
    int idx = blockIdx.x * blockDim.x + threadIdx.x;
    if (idx >= B_ * K_ * P_) return;

    int p  = idx & (P_ - 1);
    int bk = idx >> 12;
    int k  = bk % K_;
    int b  = bk / K_;

    int oy = p >> 6;
    int ox = p & 63;

    const float* offb = offsets + (size_t)b * 2 * K_ * P_;
    float dy = offb[(2 * k    ) * P_ + p];
    float dx = offb[(2 * k + 1) * P_ + p];

    float y = (float)(oy - 1 + k / KW_) + dy;
    float x = (float)(ox - 1 + k % KW_) + dx;

    float y0f = floorf(y);
    float x0f = floorf(x);
    float fy = y - y0f;
    float fx = x - x0f;
    int y0 = (int)y0f;
    int x0 = (int)x0f;
    int y1 = y0 + 1;
    int x1 = x0 + 1;

    float w00 = (1.f - fy) * (1.f - fx);
    float w01 = (1.f - fy) * fx;
    float w10 = fy * (1.f - fx);
    float w11 = fy * fx;

    bool vy0 = (y0 >= 0) & (y0 < H_);
    bool vy1 = (y1 >= 0) & (y1 < H_);
    bool vx0 = (x0 >= 0) & (x0 < W_);
    bool vx1 = (x1 >= 0) & (x1 < W_);

    if (!(vy0 & vx0)) w00 = 0.f;
    if (!(vy0 & vx1)) w01 = 0.f;
    if (!(vy1 & vx0)) w10 = 0.f;
    if (!(vy1 & vx1)) w11 = 0.f;

    int cy0 = min(max(y0, 0), H_ - 1);
    int cy1 = min(max(y1, 0), H_ - 1);
    int cx0 = min(max(x0, 0), W_ - 1);
    int cx1 = min(max(x1, 0), W_ - 1);

    int i00 = cy0 * W_ + cx0;
    int i01 = cy0 * W_ + cx1;
    int i10 = cy1 * W_ + cx0;
    int i11 = cy1 * W_ + cx1;

    const float* img = rgb + (size_t)b * CIN_ * P_;
    float* colp = g_col + (size_t)b * CK_ * P_ + (size_t)k * P_ + p;

    #pragma unroll 4
    for (int c = 0; c < CIN_; c++) {
        const float* ch = img + c * P_;
        float v = w00 * ch[i00] + w01 * ch[i01]
                + w10 * ch[i10] + w11 * ch[i11];
        colp[(size_t)c * K_ * P_] = v;
    }
}

// ---------------------------------------------------------------------------
// Kernel 2: TF32 tensor-core GEMM  out[b] = W[128x576] * col[b][576x4096] + bias
// Block: 128x128, BK=16, 256 threads (8 warps as 2m x 4n, warp tile 64x32).
// mma.sync.m16n8k8 tf32, producer-side cvt to tf32, reg-prefetch double buffer.
// ---------------------------------------------------------------------------
#define BM 128
#define BN 128
#define BKK 16
#define LDA 136   // padded row (136 mod 32 = 8 -> conflict-free frag loads)

__device__ __forceinline__ uint32_t f2tf32(float f) {
    uint32_t u;
    asm("cvt.rna.tf32.f32 %0, %1;" : "=r"(u) : "f"(f));
    return u;
}

__global__ __launch_bounds__(256)
void gemm_tf32_kernel(const float* __restrict__ weight,
                      const float* __restrict__ bias,
                      float* __restrict__ out) {
    __shared__ uint32_t As[BKK][LDA];  // [k][m_perm], tf32 bits
    __shared__ uint32_t Bs[BKK][LDA];  // [k][n], tf32 bits

    const int b   = blockIdx.z;
    const int n0  = blockIdx.x * BN;
    const int tid = threadIdx.x;
    const int lane = tid & 31;
    const int wid  = tid >> 5;
    const int warp_m = wid >> 2;      // 0..1
    const int warp_n = wid & 3;       // 0..3
    const int m_off = warp_m * 64;
    const int n_off = warp_n * 32;
    const int qq = lane >> 2;         // 0..7
    const int rr = lane & 3;          // 0..3

    const float* colb = g_col + (size_t)b * CK_ * P_;

    // Producer mappings
    const int a_row = tid >> 1;          // 0..127 (m)
    const int a_k   = (tid & 1) * 8;     // 0 or 8 (k offset)
    const int b_k   = tid >> 4;          // 0..15  (k)
    const int b_n   = (tid & 15) * 8;    // 0..120 (n offset)

    // m-permutation: within each 16-row group, pair rows (m, m+8) adjacently
    const int a_row_p = (a_row & ~15) | (((a_row & 7) << 1) | ((a_row >> 3) & 1));

    float acc[4][4][4];   // [am][bn][c0..c3]
    #pragma unroll
    for (int i = 0; i < 4; i++)
        #pragma unroll
        for (int j = 0; j < 4; j++)
            #pragma unroll
            for (int c = 0; c < 4; c++) acc[i][j][c] = 0.f;

    // prefetch first tile
    float4 pa0 = *(const float4*)&weight[(size_t)a_row * CK_ + a_k];
    float4 pa1 = *(const float4*)&weight[(size_t)a_row * CK_ + a_k + 4];
    float4 pb0 = *(const float4*)&colb[(size_t)b_k * P_ + n0 + b_n];
    float4 pb1 = *(const float4*)&colb[(size_t)b_k * P_ + n0 + b_n + 4];

    for (int k0 = 0; k0 < CK_; k0 += BKK) {
        // store prefetched tile (converted to tf32)
        As[a_k + 0][a_row_p] = f2tf32(pa0.x);
        As[a_k + 1][a_row_p] = f2tf32(pa0.y);
        As[a_k + 2][a_row_p] = f2tf32(pa0.z);
        As[a_k + 3][a_row_p] = f2tf32(pa0.w);
        As[a_k + 4][a_row_p] = f2tf32(pa1.x);
        As[a_k + 5][a_row_p] = f2tf32(pa1.y);
        As[a_k + 6][a_row_p] = f2tf32(pa1.z);
        As[a_k + 7][a_row_p] = f2tf32(pa1.w);
        Bs[b_k][b_n + 0] = f2tf32(pb0.x);
        Bs[b_k][b_n + 1] = f2tf32(pb0.y);
        Bs[b_k][b_n + 2] = f2tf32(pb0.z);
        Bs[b_k][b_n + 3] = f2tf32(pb0.w);
        Bs[b_k][b_n + 4] = f2tf32(pb1.x);
        Bs[b_k][b_n + 5] = f2tf32(pb1.y);
        Bs[b_k][b_n + 6] = f2tf32(pb1.z);
        Bs[b_k][b_n + 7] = f2tf32(pb1.w);
        __syncthreads();

        // prefetch next tile
        if (k0 + BKK < CK_) {
            pa0 = *(const float4*)&weight[(size_t)a_row * CK_ + k0 + BKK + a_k];
            pa1 = *(const float4*)&weight[(size_t)a_row * CK_ + k0 + BKK + a_k + 4];
            pb0 = *(const float4*)&colb[(size_t)(k0 + BKK + b_k) * P_ + n0 + b_n];
            pb1 = *(const float4*)&colb[(size_t)(k0 + BKK + b_k) * P_ + n0 + b_n + 4];
        }

        // compute: two k8 sub-steps
        #pragma unroll
        for (int ks = 0; ks < 2; ks++) {
            const int kk = ks * 8;
            // B fragments (shared across am)
            uint32_t bf[4][2];
            #pragma unroll
            for (int bn = 0; bn < 4; bn++) {
                bf[bn][0] = Bs[kk + rr    ][n_off + 8 * bn + qq];
                bf[bn][1] = Bs[kk + rr + 4][n_off + 8 * bn + qq];
            }
            // A fragments (paired rows via lds.64)
            uint32_t af[4][4];
            #pragma unroll
            for (int am = 0; am < 4; am++) {
                uint2 v0 = *(const uint2*)&As[kk + rr    ][m_off + 16 * am + 2 * qq];
                uint2 v1 = *(const uint2*)&As[kk + rr + 4][m_off + 16 * am + 2 * qq];
                af[am][0] = v0.x; af[am][1] = v0.y;
                af[am][2] = v1.x; af[am][3] = v1.y;
            }
            #pragma unroll
            for (int am = 0; am < 4; am++)
                #pragma unroll
                for (int bn = 0; bn < 4; bn++) {
                    asm volatile(
                        "mma.sync.aligned.m16n8k8.row.col.f32.tf32.tf32.f32 "
                        "{%0,%1,%2,%3}, {%4,%5,%6,%7}, {%8,%9}, {%0,%1,%2,%3};"
                        : "+f"(acc[am][bn][0]), "+f"(acc[am][bn][1]),
                          "+f"(acc[am][bn][2]), "+f"(acc[am][bn][3])
                        : "r"(af[am][0]), "r"(af[am][1]),
                          "r"(af[am][2]), "r"(af[am][3]),
                          "r"(bf[bn][0]), "r"(bf[bn][1]));
                }
        }
        __syncthreads();
    }

    // epilogue: bias + float2 stores
    float* outb = out + (size_t)b * COUT_ * P_;
    #pragma unroll
    for (int am = 0; am < 4; am++) {
        int m0r = m_off + 16 * am + qq;       // rows m0r and m0r+8
        float bv0 = bias[m0r];
        float bv1 = bias[m0r + 8];
        #pragma unroll
        for (int bn = 0; bn < 4; bn++) {
            int col = n0 + n_off + 8 * bn + 2 * rr;
            float2 v0 = make_float2(acc[am][bn][0] + bv0, acc[am][bn][1] + bv0);
            float2 v1 = make_float2(acc[am][bn][2] + bv1, acc[am][bn][3] + bv1);
            *(float2*)&outb[(size_t)m0r * P_ + col]       = v0;
            *(float2*)&outb[(size_t)(m0r + 8) * P_ + col] = v1;
        }
    }
}

extern "C" void kernel_launch(void* const* d_in, const int* in_sizes, int n_in,
                              void* d_out, int out_size) {
    const float* rgb     = (const float*)d_in[0];
    const float* offsets = (const float*)d_in[1];
    const float* weight  = (const float*)d_in[2];
    const float* bias    = (const float*)d_in[3];
    float* out = (float*)d_out;

    {
        int total = B_ * K_ * P_;
        int threads = 256;
        int blocks = (total + threads - 1) / threads;
        im2col_kernel<<<blocks, threads>>>(rgb, offsets);
    }
    {
        dim3 grid(P_ / BN, 1, B_);   // 32 x 1 x 8 = 256 blocks
        gemm_tf32_kernel<<<grid, 256>>>(weight, bias, out);
    }
}